// round 14
// baseline (speedup 1.0000x reference)
#include <cuda_runtime.h>
#include <cuda_bf16.h>
#include <cuda_fp16.h>
#include <math.h>
#include <stdint.h>

#define NN 50000
#define EE 800000
#define EP (EE + NN)   // 850000 edges incl. self loops
#define HEADS 8
#define HID 64
#define INF_ 256
#define OUTF 40
#define LRELU 0.2f

// ---------------- scratch ------------------------------------------------------
__device__ __half g_Wc0h[512 * 256];          // [n][k] n-major
__device__ __half g_Wc1h[512 * 512];
__device__ __half g_WcOh[64 * 512];
__device__ float  g_aPad[128];                // padded aout: [0..63]=src, [64..127]=dst
__device__ __half g_x16[(size_t)NN * INF_];
__device__ __half g_Wh16[(size_t)NN * 512];
__device__ __half g_WhO16[(size_t)NN * 64];   // layer-2 Wh fp16
__device__ __half g_h1h[(size_t)NN * 512];
__device__ __half g_h2h[(size_t)NN * 512];
__device__ float  g_ssrc[NN * HEADS];
__device__ float  g_sdst[NN * HEADS];
__device__ float  g_b[NN * HEADS];            // m + ln(s) per (dst, head)
__device__ float  g_val[(size_t)EP];          // layer-2 only
__device__ float  g_inv1[NN];                 // layer-2 inv
__device__ int    g_counts[NN];
__device__ int    g_offsets[NN + 1];
__device__ int    g_cursor[NN];
__device__ int    g_csr_src[EP];

// ---------------- prep main: packW0 + x->fp16 + zero + aPad ----------------------
// [0,512) packW0 | [512,13012) xcvt | [13012,13208) zero | 13208 aPad
__global__ void prep_main_kernel(const float* __restrict__ W0, const float* __restrict__ x,
                                 const float* __restrict__ aout) {
    int b = blockIdx.x, tid = threadIdx.x;
    if (b < 512) {                           // W0 [H,256,64] -> [n=512][k=256]
        int idx = b * 256 + tid;
        int n = idx >> 8, k = idx & 255;
        int h = n >> 6, j = n & 63;
        g_Wc0h[idx] = __float2half_rn(W0[(size_t)h * 256 * 64 + (size_t)k * 64 + j]);
    } else if (b < 13012) {
        int i = (b - 512) * 256 + tid;
        if (i < NN * INF_ / 4) {
            float4 v = __ldg((const float4*)x + i);
            __half2 lo = __floats2half2_rn(v.x, v.y);
            __half2 hi = __floats2half2_rn(v.z, v.w);
            uint2 u; u.x = *(unsigned*)&lo; u.y = *(unsigned*)&hi;
            ((uint2*)g_x16)[i] = u;
        }
    } else if (b < 13208) {
        int i = (b - 13012) * 256 + tid;
        if (i < NN) { g_counts[i] = 0; g_cursor[i] = 0; }
    } else {
        if (tid < 64)  g_aPad[tid] = (tid < OUTF) ? aout[tid] : 0.f;
        else if (tid < 128) {
            int j = tid - 64;
            g_aPad[64 + j] = (j < OUTF) ? aout[OUTF + j] : 0.f;
        }
    }
}

__global__ void packW1_kernel(const float* __restrict__ W1) {
    int idx = blockIdx.x * 256 + threadIdx.x;     // 262144
    int n = idx >> 9, k = idx & 511;
    int h = n >> 6, j = n & 63;
    g_Wc1h[idx] = __float2half_rn(W1[(size_t)h * 512 * 64 + (size_t)k * 64 + j]);
}

__global__ void packWout_kernel(const float* __restrict__ Wout) {
    int idx = blockIdx.x * 256 + threadIdx.x;     // 32768
    int n = idx >> 9, k = idx & 511;
    g_WcOh[idx] = (n < OUTF) ? __float2half_rn(Wout[k * OUTF + n]) : __float2half_rn(0.f);
}

// ---------------- cp.async helpers ---------------------------------------------
__device__ __forceinline__ void cp16(uint32_t dst, const void* src, bool pred) {
    int sz = pred ? 16 : 0;
    asm volatile("cp.async.ca.shared.global [%0], [%1], 16, %2;\n"
                 :: "r"(dst), "l"(src), "r"(sz));
}
#define CP_COMMIT() asm volatile("cp.async.commit_group;\n" ::: "memory")
#define CP_WAIT0()  asm volatile("cp.async.wait_group 0;\n" ::: "memory")
#define CP_WAIT1()  asm volatile("cp.async.wait_group 1;\n" ::: "memory")

// ---------------- FP16 GEMM body: BM=128 BN=128 BK=32, 3-stage -------------------
#define APH 40
#define A_BYTES (128 * APH * 2)
#define STAGE_BYTES (2 * A_BYTES)
#define GEMM_SMEM_BYTES (STAGE_BYTES * 3)

__device__ __forceinline__ void gemm_body_h(const __half* __restrict__ A,
                                            const __half* __restrict__ B,
                                            __half* __restrict__ C16,
                                            int M, int Nc, int K,
                                            int bxx, int byy, char* smc,
                                            const float* __restrict__ avec,
                                            float* __restrict__ ssrc,
                                            float* __restrict__ sdst,
                                            int score_mode) {        // 0 none, 1 8-head, 2 l2
    int tid = threadIdx.x;
    int wid = tid >> 5, lane = tid & 31;
    int ly = lane >> 2, lx = lane & 3;
    int wm = wid >> 1, wn = wid & 1;
    int bm = byy * 128, bn = bxx * 128;

    uint32_t sbase = (uint32_t)__cvta_generic_to_shared(smc);

    float c[2][8][4];
#pragma unroll
    for (int i = 0; i < 2; i++)
#pragma unroll
        for (int j = 0; j < 8; j++)
#pragma unroll
            for (int q = 0; q < 4; q++) c[i][j][q] = 0.f;

    int r0 = tid >> 2, q0 = tid & 3;
    int r1 = (tid + 256) >> 2, q1 = (tid + 256) & 3;
    bool ap0 = (bm + r0) < M, ap1 = (bm + r1) < M;
    bool bpr0 = (bn + r0) < Nc, bpr1 = (bn + r1) < Nc;

#define ISSUE(S, k0) do { \
        cp16(sbase + (S) * STAGE_BYTES + r0 * 80 + q0 * 16, \
             A + (size_t)(bm + r0) * K + (k0) + q0 * 8, ap0); \
        cp16(sbase + (S) * STAGE_BYTES + r1 * 80 + q1 * 16, \
             A + (size_t)(bm + r1) * K + (k0) + q1 * 8, ap1); \
        cp16(sbase + (S) * STAGE_BYTES + A_BYTES + r0 * 80 + q0 * 16, \
             B + (size_t)(bn + r0) * K + (k0) + q0 * 8, bpr0); \
        cp16(sbase + (S) * STAGE_BYTES + A_BYTES + r1 * 80 + q1 * 16, \
             B + (size_t)(bn + r1) * K + (k0) + q1 * 8, bpr1); \
        CP_COMMIT(); \
    } while (0)

#define BODY(S, t) do { \
        if ((t) + 2 < ntiles) { CP_WAIT1(); } else { CP_WAIT0(); } \
        __syncthreads(); \
        if ((t) + 2 < ntiles) ISSUE(((S) + 2) % 3, ((t) + 2) * 32); \
        const __half* Asc = (const __half*)(smc + (S) * STAGE_BYTES); \
        const __half* Bsc = (const __half*)(smc + (S) * STAGE_BYTES + A_BYTES); \
        _Pragma("unroll") \
        for (int kk = 0; kk < 32; kk += 16) { \
            unsigned af[2][4]; \
            _Pragma("unroll") \
            for (int mt = 0; mt < 2; mt++) { \
                int mrow = wm * 32 + mt * 16 + ly; \
                af[mt][0] = *(const unsigned*)&Asc[(mrow) * APH + kk + 2 * lx]; \
                af[mt][1] = *(const unsigned*)&Asc[(mrow + 8) * APH + kk + 2 * lx]; \
                af[mt][2] = *(const unsigned*)&Asc[(mrow) * APH + kk + 8 + 2 * lx]; \
                af[mt][3] = *(const unsigned*)&Asc[(mrow + 8) * APH + kk + 8 + 2 * lx]; \
            } \
            unsigned bf[8][2]; \
            _Pragma("unroll") \
            for (int nt = 0; nt < 8; nt++) { \
                int ncol = wn * 64 + nt * 8 + ly; \
                bf[nt][0] = *(const unsigned*)&Bsc[(ncol) * APH + kk + 2 * lx]; \
                bf[nt][1] = *(const unsigned*)&Bsc[(ncol) * APH + kk + 8 + 2 * lx]; \
            } \
            _Pragma("unroll") \
            for (int mt = 0; mt < 2; mt++) \
                _Pragma("unroll") \
                for (int nt = 0; nt < 8; nt++) { \
                    asm volatile( \
                        "mma.sync.aligned.m16n8k16.row.col.f32.f16.f16.f32 " \
                        "{%0,%1,%2,%3}, {%4,%5,%6,%7}, {%8,%9}, {%0,%1,%2,%3};\n" \
                        : "+f"(c[mt][nt][0]), "+f"(c[mt][nt][1]), \
                          "+f"(c[mt][nt][2]), "+f"(c[mt][nt][3]) \
                        : "r"(af[mt][0]), "r"(af[mt][1]), "r"(af[mt][2]), "r"(af[mt][3]), \
                          "r"(bf[nt][0]), "r"(bf[nt][1])); \
                } \
        } \
    } while (0)

    int ntiles = K / 32;
    ISSUE(0, 0);
    ISSUE(1, 32);

    int nfull = ntiles - (ntiles % 3);
    for (int t = 0; t < nfull; t += 3) {
        BODY(0, t);
        BODY(1, t + 1);
        BODY(2, t + 2);
    }
    if (ntiles % 3 >= 1) BODY(0, nfull);
    if (ntiles % 3 == 2) BODY(1, nfull + 1);
#undef BODY
#undef ISSUE

    __syncthreads();
    if (C16) {
#pragma unroll
        for (int mt = 0; mt < 2; mt++)
#pragma unroll
            for (int nt = 0; nt < 8; nt++) {
                int rr0 = bm + wm * 32 + mt * 16 + ly;
                int col = bn + wn * 64 + nt * 8 + 2 * lx;
                if (col < Nc) {
                    if (rr0 < M)
                        *(__half2*)(C16 + (size_t)rr0 * Nc + col) =
                            __floats2half2_rn(c[mt][nt][0], c[mt][nt][1]);
                    int rr1 = rr0 + 8;
                    if (rr1 < M)
                        *(__half2*)(C16 + (size_t)rr1 * Nc + col) =
                            __floats2half2_rn(c[mt][nt][2], c[mt][nt][3]);
                }
            }
    }

    // ---- fused attention-score epilogues ----
    if (score_mode == 1 || (score_mode == 2 && wn == 0)) {
        const float* aH = (score_mode == 1) ? (avec + (2 * bxx + wn) * 128) : avec;
        float accs[2][2], accd[2][2];
#pragma unroll
        for (int mt = 0; mt < 2; mt++) { accs[mt][0] = accs[mt][1] = accd[mt][0] = accd[mt][1] = 0.f; }
#pragma unroll
        for (int nt = 0; nt < 8; nt++) {
            int jc = nt * 8 + 2 * lx;
            float a0s = __ldg(aH + jc), a1s = __ldg(aH + jc + 1);
            float a0d = __ldg(aH + 64 + jc), a1d = __ldg(aH + 64 + jc + 1);
#pragma unroll
            for (int mt = 0; mt < 2; mt++) {
                accs[mt][0] += c[mt][nt][0] * a0s + c[mt][nt][1] * a1s;
                accd[mt][0] += c[mt][nt][0] * a0d + c[mt][nt][1] * a1d;
                accs[mt][1] += c[mt][nt][2] * a0s + c[mt][nt][3] * a1s;
                accd[mt][1] += c[mt][nt][2] * a0d + c[mt][nt][3] * a1d;
            }
        }
#pragma unroll
        for (int mt = 0; mt < 2; mt++)
#pragma unroll
            for (int hf = 0; hf < 2; hf++) {
                accs[mt][hf] += __shfl_xor_sync(0xffffffffu, accs[mt][hf], 1);
                accs[mt][hf] += __shfl_xor_sync(0xffffffffu, accs[mt][hf], 2);
                accd[mt][hf] += __shfl_xor_sync(0xffffffffu, accd[mt][hf], 1);
                accd[mt][hf] += __shfl_xor_sync(0xffffffffu, accd[mt][hf], 2);
            }
        if (lx == 0) {
#pragma unroll
            for (int mt = 0; mt < 2; mt++)
#pragma unroll
                for (int hf = 0; hf < 2; hf++) {
                    int row = bm + wm * 32 + mt * 16 + ly + hf * 8;
                    if (row < M) {
                        if (score_mode == 1) {
                            int head = 2 * bxx + wn;
                            ssrc[row * 8 + head] = accs[mt][hf];
                            sdst[row * 8 + head] = accd[mt][hf];
                        } else {
                            ssrc[row] = accs[mt][hf];
                            sdst[row] = accd[mt][hf];
                        }
                    }
                }
        }
    }
}

// ---------------- standalone GEMM ------------------------------------------------
__global__ __launch_bounds__(256) void gemm_h_kernel(const __half* __restrict__ A,
                                                     const __half* __restrict__ B,
                                                     __half* __restrict__ C16,
                                                     int M, int Nc, int K,
                                                     const float* __restrict__ avec,
                                                     float* __restrict__ ssrc,
                                                     float* __restrict__ sdst,
                                                     int score_mode) {
    extern __shared__ char smc[];
    gemm_body_h(A, B, C16, M, Nc, K, blockIdx.x, blockIdx.y, smc, avec, ssrc, sdst, score_mode);
}

// ---------------- fused hist + gemm0 ---------------------------------------------
#define HIST_BLKS 3321
__global__ __launch_bounds__(256) void hist_gemm_kernel(const int* __restrict__ ei,
                                                        const __half* __restrict__ A,
                                                        const __half* __restrict__ B,
                                                        __half* __restrict__ C16,
                                                        const float* __restrict__ avec,
                                                        float* __restrict__ ssrc,
                                                        float* __restrict__ sdst) {
    extern __shared__ char smc[];
    int b = blockIdx.x;
    if (b < HIST_BLKS) {
        int e = b * 256 + threadIdx.x;
        if (e < EP) {
            int dst = (e < EE) ? ei[EE + e] : (e - EE);
            atomicAdd(&g_counts[dst], 1);
        }
        return;
    }
    int g = b - HIST_BLKS;
    gemm_body_h(A, B, C16, NN, 512, INF_, g & 3, g >> 2, smc, avec, ssrc, sdst, 1);
}

// ---------------- fast single-block scan ------------------------------------------
__global__ void scan_kernel() {
    __shared__ int ws[33];
    int tid = threadIdx.x;
    int w = tid >> 5, lane = tid & 31;
    int carry = 0;
    for (int base = 0; base < NN; base += 1024) {
        int i = base + tid;
        int x = (i < NN) ? g_counts[i] : 0;
        int inc = x;
#pragma unroll
        for (int o = 1; o < 32; o <<= 1) {
            int t = __shfl_up_sync(0xffffffffu, inc, o);
            if (lane >= o) inc += t;
        }
        if (lane == 31) ws[w] = inc;
        __syncthreads();
        if (w == 0) {
            int t = (lane < 32) ? ws[lane] : 0;
            int ti = t;
#pragma unroll
            for (int o = 1; o < 32; o <<= 1) {
                int u = __shfl_up_sync(0xffffffffu, ti, o);
                if (lane >= o) ti += u;
            }
            ws[lane] = ti - t;
            if (lane == 31) ws[32] = ti;
        }
        __syncthreads();
        int excl = inc - x + ws[w] + carry;
        if (i < NN) g_offsets[i] = excl;
        carry += ws[32];
        __syncthreads();
    }
    if (tid == 0) g_offsets[NN] = carry;
}

// ---------------- fill -------------------------------------------------------------
__global__ void fill_kernel(const int* __restrict__ ei) {
    int e = blockIdx.x * blockDim.x + threadIdx.x;
    if (e >= EP) return;
    int src = (e < EE) ? ei[e] : (e - EE);
    int dst = (e < EE) ? ei[EE + e] : (e - EE);
    int pos = g_offsets[dst] + atomicAdd(&g_cursor[dst], 1);
    g_csr_src[pos] = src;
}

// ---------------- alpha8: compute b = m + ln(sum) per (dst, head) ------------------
__global__ void alpha8_kernel(const float* __restrict__ ssrc, const float* __restrict__ sdst,
                              float* __restrict__ bout) {
    int w = (blockIdx.x * blockDim.x + threadIdx.x) >> 5;
    int lane = threadIdx.x & 31;
    if (w >= NN) return;
    int beg = g_offsets[w], end = g_offsets[w + 1];
    float4 d0 = __ldg((const float4*)(sdst + w * 8));
    float4 d1 = __ldg((const float4*)(sdst + w * 8 + 4));
    float sdh[8] = {d0.x, d0.y, d0.z, d0.w, d1.x, d1.y, d1.z, d1.w};
    float m[8];
#pragma unroll
    for (int h = 0; h < 8; h++) m[h] = -1e30f;

    for (int p = beg + lane; p < end; p += 32) {
        int src = g_csr_src[p];
        float4 s0 = __ldg((const float4*)(ssrc + src * 8));
        float4 s1 = __ldg((const float4*)(ssrc + src * 8 + 4));
        float sv[8] = {s0.x, s0.y, s0.z, s0.w, s1.x, s1.y, s1.z, s1.w};
#pragma unroll
        for (int h = 0; h < 8; h++) {
            float v = sv[h] + sdh[h];
            v = v > 0.f ? v : LRELU * v;
            m[h] = fmaxf(m[h], v);
        }
    }
#pragma unroll
    for (int h = 0; h < 8; h++)
#pragma unroll
        for (int o = 16; o; o >>= 1) m[h] = fmaxf(m[h], __shfl_xor_sync(0xffffffffu, m[h], o));

    float s[8];
#pragma unroll
    for (int h = 0; h < 8; h++) s[h] = 0.f;
    for (int p = beg + lane; p < end; p += 32) {
        int src = g_csr_src[p];
        float4 s0 = __ldg((const float4*)(ssrc + src * 8));
        float4 s1 = __ldg((const float4*)(ssrc + src * 8 + 4));
        float sv[8] = {s0.x, s0.y, s0.z, s0.w, s1.x, s1.y, s1.z, s1.w};
#pragma unroll
        for (int h = 0; h < 8; h++) {
            float v = sv[h] + sdh[h];
            v = v > 0.f ? v : LRELU * v;
            s[h] += __expf(v - m[h]);
        }
    }
#pragma unroll
    for (int h = 0; h < 8; h++)
#pragma unroll
        for (int o = 16; o; o >>= 1) s[h] += __shfl_xor_sync(0xffffffffu, s[h], o);
    if (lane == 0) {
#pragma unroll
        for (int h = 0; h < 8; h++) bout[w * 8 + h] = m[h] + __logf(s[h]);
    }
}

// ---------------- alpha1 (layer 2, writes normalized val) --------------------------
__global__ void alpha1_kernel(const float* __restrict__ ssrc, const float* __restrict__ sdst,
                              float* __restrict__ val, float* __restrict__ inv) {
    int w = (blockIdx.x * blockDim.x + threadIdx.x) >> 5;
    int lane = threadIdx.x & 31;
    if (w >= NN) return;
    int beg = g_offsets[w], end = g_offsets[w + 1];
    float sdh = __ldg(sdst + w);
    float m = -1e30f;
    for (int p = beg + lane; p < end; p += 32) {
        float v = __ldg(ssrc + g_csr_src[p]) + sdh;
        v = v > 0.f ? v : LRELU * v;
        m = fmaxf(m, v);
    }
#pragma unroll
    for (int o = 16; o; o >>= 1) m = fmaxf(m, __shfl_xor_sync(0xffffffffu, m, o));
    float s = 0.f;
    for (int p = beg + lane; p < end; p += 32) {
        float v = __ldg(ssrc + g_csr_src[p]) + sdh;
        v = v > 0.f ? v : LRELU * v;
        float ex = __expf(v - m);
        val[p] = ex;
        s += ex;
    }
#pragma unroll
    for (int o = 16; o; o >>= 1) s += __shfl_xor_sync(0xffffffffu, s, o);
    if (lane == 0) inv[w] = 1.0f / s;
}

// ---------------- aggregation, Ftot=512, on-the-fly alpha --------------------------
__global__ __launch_bounds__(128) void aggregate512_kernel(const __half* __restrict__ Wh16,
                                                           const float* __restrict__ ssrc,
                                                           const float* __restrict__ sdst,
                                                           const float* __restrict__ bvec,
                                                           __half* __restrict__ out16) {
    int d = blockIdx.x;
    int t = threadIdx.x;
    int h = t >> 4;
    int lane = t & 31;
    int lane16 = t & 15;
    int beg = g_offsets[d], end = g_offsets[d + 1];
    const uint2* W2 = (const uint2*)Wh16;
    float sdh = __ldg(&sdst[d * 8 + h]);
    float bb = __ldg(&bvec[d * 8 + h]);
    float4 acc = make_float4(0.f, 0.f, 0.f, 0.f);
    for (int p0 = beg; p0 < end; p0 += 16) {
        int cnt = end - p0; if (cnt > 16) cnt = 16;
        float exv = 0.f;
        if (lane16 < cnt) {
            int srcl = g_csr_src[p0 + lane16];
            float v = __ldg(&ssrc[srcl * 8 + h]) + sdh;
            v = v > 0.f ? v : LRELU * v;
            exv = __expf(v - bb);
        }
        for (int j = 0; j < cnt; j++) {
            float e = __shfl_sync(0xffffffffu, exv, (lane & 16) | j);
            int sj = g_csr_src[p0 + j];
            uint2 u = __ldg(&W2[(size_t)sj * 128 + t]);
            float2 a0 = __half22float2(*(__half2*)&u.x);
            float2 b0 = __half22float2(*(__half2*)&u.y);
            acc.x += e * a0.x;
            acc.y += e * a0.y;
            acc.z += e * b0.x;
            acc.w += e * b0.y;
        }
    }
    acc.x = acc.x > 0.f ? acc.x : expm1f(acc.x);
    acc.y = acc.y > 0.f ? acc.y : expm1f(acc.y);
    acc.z = acc.z > 0.f ? acc.z : expm1f(acc.z);
    acc.w = acc.w > 0.f ? acc.w : expm1f(acc.w);
    __half2 lo = __floats2half2_rn(acc.x, acc.y);
    __half2 hi = __floats2half2_rn(acc.z, acc.w);
    uint2 u;
    u.x = *(unsigned*)&lo; u.y = *(unsigned*)&hi;
    ((uint2*)out16)[(size_t)d * 128 + t] = u;
}

// ---------------- aggregation layer 2 + fused elu + log_softmax --------------------
__global__ __launch_bounds__(64) void aggregate_l2_final_kernel(const __half* __restrict__ WhO,
                                                                const float* __restrict__ val,
                                                                const float* __restrict__ inv,
                                                                float* __restrict__ out) {
    __shared__ float wred[2][2];
    int d = blockIdx.x;
    int f = threadIdx.x;
    int wp_ = f >> 5, lane = f & 31;
    int beg = g_offsets[d], end = g_offsets[d + 1];
    float acc = 0.f;
    for (int p = beg; p < end; p++) {
        int src = g_csr_src[p];
        float ex = __ldg(&val[p]);
        if (f < OUTF) acc += ex * __half2float(WhO[(size_t)src * 64 + f]);
    }
    float v = -1e30f;
    if (f < OUTF) {
        float o = acc * __ldg(&inv[d]);
        v = o > 0.f ? o : expm1f(o);
    }
    float m = v;
#pragma unroll
    for (int o = 16; o; o >>= 1) m = fmaxf(m, __shfl_xor_sync(0xffffffffu, m, o));
    if (lane == 0) wred[0][wp_] = m;
    __syncthreads();
    m = fmaxf(wred[0][0], wred[0][1]);
    float e = (f < OUTF) ? __expf(v - m) : 0.f;
    float s = e;
#pragma unroll
    for (int o = 16; o; o >>= 1) s += __shfl_xor_sync(0xffffffffu, s, o);
    if (lane == 0) wred[1][wp_] = s;
    __syncthreads();
    s = wred[1][0] + wred[1][1];
    float l = logf(s) + m;
    if (f < OUTF) out[(size_t)d * OUTF + f] = v - l;
}

// ---------------- host orchestration -----------------------------------------------
extern "C" void kernel_launch(void* const* d_in, const int* in_sizes, int n_in,
                              void* d_out, int out_size) {
    const float* x    = (const float*)d_in[0];
    const int*   ei   = (const int*)d_in[1];
    const float* W0   = (const float*)d_in[2];
    const float* a0   = (const float*)d_in[3];
    const float* W1   = (const float*)d_in[4];
    const float* a1   = (const float*)d_in[5];
    const float* Wout = (const float*)d_in[6];
    const float* aout = (const float*)d_in[7];
    float* out = (float*)d_out;

    __half *Wc0h, *Wc1h, *WcOh, *x16, *Wh16, *WhO16, *h1h, *h2h;
    float *aPad, *ssrc, *sdst, *bvec, *val, *inv1;
    cudaGetSymbolAddress((void**)&Wc0h, g_Wc0h);
    cudaGetSymbolAddress((void**)&Wc1h, g_Wc1h);
    cudaGetSymbolAddress((void**)&WcOh, g_WcOh);
    cudaGetSymbolAddress((void**)&aPad, g_aPad);
    cudaGetSymbolAddress((void**)&x16, g_x16);
    cudaGetSymbolAddress((void**)&Wh16, g_Wh16);
    cudaGetSymbolAddress((void**)&WhO16, g_WhO16);
    cudaGetSymbolAddress((void**)&h1h, g_h1h);
    cudaGetSymbolAddress((void**)&h2h, g_h2h);
    cudaGetSymbolAddress((void**)&ssrc, g_ssrc);
    cudaGetSymbolAddress((void**)&sdst, g_sdst);
    cudaGetSymbolAddress((void**)&bvec, g_b);
    cudaGetSymbolAddress((void**)&val, g_val);
    cudaGetSymbolAddress((void**)&inv1, g_inv1);

    static int smem_set = 0;
    if (!smem_set) {
        cudaFuncSetAttribute(gemm_h_kernel,
                             cudaFuncAttributeMaxDynamicSharedMemorySize, GEMM_SMEM_BYTES);
        cudaFuncSetAttribute(hist_gemm_kernel,
                             cudaFuncAttributeMaxDynamicSharedMemorySize, GEMM_SMEM_BYTES);
        smem_set = 1;
    }

    const int TB = 256;
    dim3 gh_grid(4, (NN + 127) / 128);
    dim3 gh_grid_out(1, (NN + 127) / 128);

    // 1-3: prep pieces (launch #4 = hist_gemm for ncu)
    prep_main_kernel<<<13209, TB>>>(W0, x, aout);
    packW1_kernel<<<1024, TB>>>(W1);
    packWout_kernel<<<128, TB>>>(Wout);
    // 4: hist || gemm0 (+scores l0)
    hist_gemm_kernel<<<HIST_BLKS + 1564, TB, GEMM_SMEM_BYTES>>>(ei, x16, Wc0h, Wh16, a0, ssrc, sdst);
    // 5: scan, 6: fill
    scan_kernel<<<1, 1024>>>();
    fill_kernel<<<(EP + TB - 1) / TB, TB>>>(ei);
    // 7-8: layer-0 edge phase
    alpha8_kernel<<<(NN + 7) / 8, 256>>>(ssrc, sdst, bvec);
    aggregate512_kernel<<<NN, 128>>>(Wh16, ssrc, sdst, bvec, h1h);

    // ---- layer 1 ----
    gemm_h_kernel<<<gh_grid, 256, GEMM_SMEM_BYTES>>>(h1h, Wc1h, Wh16, NN, 512, 512,
                                                     a1, ssrc, sdst, 1);
    alpha8_kernel<<<(NN + 7) / 8, 256>>>(ssrc, sdst, bvec);
    aggregate512_kernel<<<NN, 128>>>(Wh16, ssrc, sdst, bvec, h2h);

    // ---- layer 2 (scores fused into GEMM epilogue) ----
    gemm_h_kernel<<<gh_grid_out, 256, GEMM_SMEM_BYTES>>>(h2h, WcOh, WhO16, NN, 64, 512,
                                                         aPad, ssrc, sdst, 2);
    alpha1_kernel<<<(NN + 7) / 8, 256>>>(ssrc, sdst, val, inv1);
    aggregate_l2_final_kernel<<<NN, 64>>>(WhO16, val, inv1, out);
}

// round 15
// speedup vs baseline: 1.0267x; 1.0267x over previous
#include <cuda_runtime.h>
#include <cuda_bf16.h>
#include <cuda_fp16.h>
#include <math.h>
#include <stdint.h>

#define NN 50000
#define EE 800000
#define EP (EE + NN)   // 850000 edges incl. self loops
#define HEADS 8
#define HID 64
#define INF_ 256
#define OUTF 40
#define LRELU 0.2f

// ---------------- scratch ------------------------------------------------------
__device__ __half g_Wc0h[512 * 256];          // [n][k] n-major
__device__ __half g_Wc1h[512 * 512];
__device__ __half g_WcOh[64 * 512];
__device__ float  g_aPad[128];                // padded aout: [0..63]=src, [64..127]=dst
__device__ __half g_x16[(size_t)NN * INF_];
__device__ __half g_Wh16[(size_t)NN * 512];
__device__ __half g_WhO16[(size_t)NN * 64];   // layer-2 Wh fp16
__device__ __half g_h1h[(size_t)NN * 512];
__device__ __half g_h2h[(size_t)NN * 512];
__device__ float  g_ssrc[NN * HEADS];
__device__ float  g_sdst[NN * HEADS];
__device__ float  g_val[(size_t)EP * HEADS];  // [h*EP + p]
__device__ float  g_inv[NN * HEADS];
__device__ int    g_counts[NN];
__device__ int    g_offsets[NN + 1];
__device__ int    g_cursor[NN];
__device__ int    g_csr_src[EP];

// ---------------- prep main: packW0 + x->fp16 + zero + aPad ----------------------
__global__ void prep_main_kernel(const float* __restrict__ W0, const float* __restrict__ x,
                                 const float* __restrict__ aout) {
    int b = blockIdx.x, tid = threadIdx.x;
    if (b < 512) {                           // W0 [H,256,64] -> [n=512][k=256]
        int idx = b * 256 + tid;
        int n = idx >> 8, k = idx & 255;
        int h = n >> 6, j = n & 63;
        g_Wc0h[idx] = __float2half_rn(W0[(size_t)h * 256 * 64 + (size_t)k * 64 + j]);
    } else if (b < 13012) {
        int i = (b - 512) * 256 + tid;
        if (i < NN * INF_ / 4) {
            float4 v = __ldg((const float4*)x + i);
            __half2 lo = __floats2half2_rn(v.x, v.y);
            __half2 hi = __floats2half2_rn(v.z, v.w);
            uint2 u; u.x = *(unsigned*)&lo; u.y = *(unsigned*)&hi;
            ((uint2*)g_x16)[i] = u;
        }
    } else if (b < 13208) {
        int i = (b - 13012) * 256 + tid;
        if (i < NN) { g_counts[i] = 0; g_cursor[i] = 0; }
    } else {
        if (tid < 64)  g_aPad[tid] = (tid < OUTF) ? aout[tid] : 0.f;
        else if (tid < 128) {
            int j = tid - 64;
            g_aPad[64 + j] = (j < OUTF) ? aout[OUTF + j] : 0.f;
        }
    }
}

__global__ void packW1_kernel(const float* __restrict__ W1) {
    int idx = blockIdx.x * 256 + threadIdx.x;     // 262144
    int n = idx >> 9, k = idx & 511;
    int h = n >> 6, j = n & 63;
    g_Wc1h[idx] = __float2half_rn(W1[(size_t)h * 512 * 64 + (size_t)k * 64 + j]);
}

__global__ void packWout_kernel(const float* __restrict__ Wout) {
    int idx = blockIdx.x * 256 + threadIdx.x;     // 32768
    int n = idx >> 9, k = idx & 511;
    g_WcOh[idx] = (n < OUTF) ? __float2half_rn(Wout[k * OUTF + n]) : __float2half_rn(0.f);
}

// ---------------- cp.async helpers ---------------------------------------------
__device__ __forceinline__ void cp16(uint32_t dst, const void* src, bool pred) {
    int sz = pred ? 16 : 0;
    asm volatile("cp.async.ca.shared.global [%0], [%1], 16, %2;\n"
                 :: "r"(dst), "l"(src), "r"(sz));
}
#define CP_COMMIT() asm volatile("cp.async.commit_group;\n" ::: "memory")
#define CP_WAIT0()  asm volatile("cp.async.wait_group 0;\n" ::: "memory")
#define CP_WAIT1()  asm volatile("cp.async.wait_group 1;\n" ::: "memory")

// ---------------- FP16 GEMM body: BM=128 BN=128 BK=32, 3-stage -------------------
#define APH 40
#define A_BYTES (128 * APH * 2)
#define STAGE_BYTES (2 * A_BYTES)
#define GEMM_SMEM_BYTES (STAGE_BYTES * 3)

__device__ __forceinline__ void gemm_body_h(const __half* __restrict__ A,
                                            const __half* __restrict__ B,
                                            __half* __restrict__ C16,
                                            int M, int Nc, int K,
                                            int bxx, int byy, char* smc,
                                            const float* __restrict__ avec,
                                            float* __restrict__ ssrc,
                                            float* __restrict__ sdst,
                                            int score_mode) {        // 0 none, 1 8-head, 2 l2
    int tid = threadIdx.x;
    int wid = tid >> 5, lane = tid & 31;
    int ly = lane >> 2, lx = lane & 3;
    int wm = wid >> 1, wn = wid & 1;
    int bm = byy * 128, bn = bxx * 128;

    uint32_t sbase = (uint32_t)__cvta_generic_to_shared(smc);

    float c[2][8][4];
#pragma unroll
    for (int i = 0; i < 2; i++)
#pragma unroll
        for (int j = 0; j < 8; j++)
#pragma unroll
            for (int q = 0; q < 4; q++) c[i][j][q] = 0.f;

    int r0 = tid >> 2, q0 = tid & 3;
    int r1 = (tid + 256) >> 2, q1 = (tid + 256) & 3;
    bool ap0 = (bm + r0) < M, ap1 = (bm + r1) < M;
    bool bpr0 = (bn + r0) < Nc, bpr1 = (bn + r1) < Nc;

#define ISSUE(S, k0) do { \
        cp16(sbase + (S) * STAGE_BYTES + r0 * 80 + q0 * 16, \
             A + (size_t)(bm + r0) * K + (k0) + q0 * 8, ap0); \
        cp16(sbase + (S) * STAGE_BYTES + r1 * 80 + q1 * 16, \
             A + (size_t)(bm + r1) * K + (k0) + q1 * 8, ap1); \
        cp16(sbase + (S) * STAGE_BYTES + A_BYTES + r0 * 80 + q0 * 16, \
             B + (size_t)(bn + r0) * K + (k0) + q0 * 8, bpr0); \
        cp16(sbase + (S) * STAGE_BYTES + A_BYTES + r1 * 80 + q1 * 16, \
             B + (size_t)(bn + r1) * K + (k0) + q1 * 8, bpr1); \
        CP_COMMIT(); \
    } while (0)

#define BODY(S, t) do { \
        if ((t) + 2 < ntiles) { CP_WAIT1(); } else { CP_WAIT0(); } \
        __syncthreads(); \
        if ((t) + 2 < ntiles) ISSUE(((S) + 2) % 3, ((t) + 2) * 32); \
        const __half* Asc = (const __half*)(smc + (S) * STAGE_BYTES); \
        const __half* Bsc = (const __half*)(smc + (S) * STAGE_BYTES + A_BYTES); \
        _Pragma("unroll") \
        for (int kk = 0; kk < 32; kk += 16) { \
            unsigned af[2][4]; \
            _Pragma("unroll") \
            for (int mt = 0; mt < 2; mt++) { \
                int mrow = wm * 32 + mt * 16 + ly; \
                af[mt][0] = *(const unsigned*)&Asc[(mrow) * APH + kk + 2 * lx]; \
                af[mt][1] = *(const unsigned*)&Asc[(mrow + 8) * APH + kk + 2 * lx]; \
                af[mt][2] = *(const unsigned*)&Asc[(mrow) * APH + kk + 8 + 2 * lx]; \
                af[mt][3] = *(const unsigned*)&Asc[(mrow + 8) * APH + kk + 8 + 2 * lx]; \
            } \
            unsigned bf[8][2]; \
            _Pragma("unroll") \
            for (int nt = 0; nt < 8; nt++) { \
                int ncol = wn * 64 + nt * 8 + ly; \
                bf[nt][0] = *(const unsigned*)&Bsc[(ncol) * APH + kk + 2 * lx]; \
                bf[nt][1] = *(const unsigned*)&Bsc[(ncol) * APH + kk + 8 + 2 * lx]; \
            } \
            _Pragma("unroll") \
            for (int mt = 0; mt < 2; mt++) \
                _Pragma("unroll") \
                for (int nt = 0; nt < 8; nt++) { \
                    asm volatile( \
                        "mma.sync.aligned.m16n8k16.row.col.f32.f16.f16.f32 " \
                        "{%0,%1,%2,%3}, {%4,%5,%6,%7}, {%8,%9}, {%0,%1,%2,%3};\n" \
                        : "+f"(c[mt][nt][0]), "+f"(c[mt][nt][1]), \
                          "+f"(c[mt][nt][2]), "+f"(c[mt][nt][3]) \
                        : "r"(af[mt][0]), "r"(af[mt][1]), "r"(af[mt][2]), "r"(af[mt][3]), \
                          "r"(bf[nt][0]), "r"(bf[nt][1])); \
                } \
        } \
    } while (0)

    int ntiles = K / 32;
    ISSUE(0, 0);
    ISSUE(1, 32);

    int nfull = ntiles - (ntiles % 3);
    for (int t = 0; t < nfull; t += 3) {
        BODY(0, t);
        BODY(1, t + 1);
        BODY(2, t + 2);
    }
    if (ntiles % 3 >= 1) BODY(0, nfull);
    if (ntiles % 3 == 2) BODY(1, nfull + 1);
#undef BODY
#undef ISSUE

    __syncthreads();
    if (C16) {
#pragma unroll
        for (int mt = 0; mt < 2; mt++)
#pragma unroll
            for (int nt = 0; nt < 8; nt++) {
                int rr0 = bm + wm * 32 + mt * 16 + ly;
                int col = bn + wn * 64 + nt * 8 + 2 * lx;
                if (col < Nc) {
                    if (rr0 < M)
                        *(__half2*)(C16 + (size_t)rr0 * Nc + col) =
                            __floats2half2_rn(c[mt][nt][0], c[mt][nt][1]);
                    int rr1 = rr0 + 8;
                    if (rr1 < M)
                        *(__half2*)(C16 + (size_t)rr1 * Nc + col) =
                            __floats2half2_rn(c[mt][nt][2], c[mt][nt][3]);
                }
            }
    }

    // ---- fused attention-score epilogues ----
    if (score_mode == 1 || (score_mode == 2 && wn == 0)) {
        const float* aH = (score_mode == 1) ? (avec + (2 * bxx + wn) * 128) : avec;
        float accs[2][2], accd[2][2];
#pragma unroll
        for (int mt = 0; mt < 2; mt++) { accs[mt][0] = accs[mt][1] = accd[mt][0] = accd[mt][1] = 0.f; }
#pragma unroll
        for (int nt = 0; nt < 8; nt++) {
            int jc = nt * 8 + 2 * lx;
            float a0s = __ldg(aH + jc), a1s = __ldg(aH + jc + 1);
            float a0d = __ldg(aH + 64 + jc), a1d = __ldg(aH + 64 + jc + 1);
#pragma unroll
            for (int mt = 0; mt < 2; mt++) {
                accs[mt][0] += c[mt][nt][0] * a0s + c[mt][nt][1] * a1s;
                accd[mt][0] += c[mt][nt][0] * a0d + c[mt][nt][1] * a1d;
                accs[mt][1] += c[mt][nt][2] * a0s + c[mt][nt][3] * a1s;
                accd[mt][1] += c[mt][nt][2] * a0d + c[mt][nt][3] * a1d;
            }
        }
#pragma unroll
        for (int mt = 0; mt < 2; mt++)
#pragma unroll
            for (int hf = 0; hf < 2; hf++) {
                accs[mt][hf] += __shfl_xor_sync(0xffffffffu, accs[mt][hf], 1);
                accs[mt][hf] += __shfl_xor_sync(0xffffffffu, accs[mt][hf], 2);
                accd[mt][hf] += __shfl_xor_sync(0xffffffffu, accd[mt][hf], 1);
                accd[mt][hf] += __shfl_xor_sync(0xffffffffu, accd[mt][hf], 2);
            }
        if (lx == 0) {
#pragma unroll
            for (int mt = 0; mt < 2; mt++)
#pragma unroll
                for (int hf = 0; hf < 2; hf++) {
                    int row = bm + wm * 32 + mt * 16 + ly + hf * 8;
                    if (row < M) {
                        if (score_mode == 1) {
                            int head = 2 * bxx + wn;
                            ssrc[row * 8 + head] = accs[mt][hf];
                            sdst[row * 8 + head] = accd[mt][hf];
                        } else {
                            ssrc[row] = accs[mt][hf];
                            sdst[row] = accd[mt][hf];
                        }
                    }
                }
        }
    }
}

// ---------------- standalone GEMM ------------------------------------------------
__global__ __launch_bounds__(256) void gemm_h_kernel(const __half* __restrict__ A,
                                                     const __half* __restrict__ B,
                                                     __half* __restrict__ C16,
                                                     int M, int Nc, int K,
                                                     const float* __restrict__ avec,
                                                     float* __restrict__ ssrc,
                                                     float* __restrict__ sdst,
                                                     int score_mode) {
    extern __shared__ char smc[];
    gemm_body_h(A, B, C16, M, Nc, K, blockIdx.x, blockIdx.y, smc, avec, ssrc, sdst, score_mode);
}

// ---------------- fused hist + gemm0 ---------------------------------------------
#define HIST_BLKS 3321
__global__ __launch_bounds__(256) void hist_gemm_kernel(const int* __restrict__ ei,
                                                        const __half* __restrict__ A,
                                                        const __half* __restrict__ B,
                                                        __half* __restrict__ C16,
                                                        const float* __restrict__ avec,
                                                        float* __restrict__ ssrc,
                                                        float* __restrict__ sdst) {
    extern __shared__ char smc[];
    int b = blockIdx.x;
    if (b < HIST_BLKS) {
        int e = b * 256 + threadIdx.x;
        if (e < EP) {
            int dst = (e < EE) ? ei[EE + e] : (e - EE);
            atomicAdd(&g_counts[dst], 1);
        }
        return;
    }
    int g = b - HIST_BLKS;
    gemm_body_h(A, B, C16, NN, 512, INF_, g & 3, g >> 2, smc, avec, ssrc, sdst, 1);
}

// ---------------- fast single-block scan ------------------------------------------
__global__ void scan_kernel() {
    __shared__ int ws[33];
    int tid = threadIdx.x;
    int w = tid >> 5, lane = tid & 31;
    int carry = 0;
    for (int base = 0; base < NN; base += 1024) {
        int i = base + tid;
        int x = (i < NN) ? g_counts[i] : 0;
        int inc = x;
#pragma unroll
        for (int o = 1; o < 32; o <<= 1) {
            int t = __shfl_up_sync(0xffffffffu, inc, o);
            if (lane >= o) inc += t;
        }
        if (lane == 31) ws[w] = inc;
        __syncthreads();
        if (w == 0) {
            int t = (lane < 32) ? ws[lane] : 0;
            int ti = t;
#pragma unroll
            for (int o = 1; o < 32; o <<= 1) {
                int u = __shfl_up_sync(0xffffffffu, ti, o);
                if (lane >= o) ti += u;
            }
            ws[lane] = ti - t;
            if (lane == 31) ws[32] = ti;
        }
        __syncthreads();
        int excl = inc - x + ws[w] + carry;
        if (i < NN) g_offsets[i] = excl;
        carry += ws[32];
        __syncthreads();
    }
    if (tid == 0) g_offsets[NN] = carry;
}

// ---------------- fill -------------------------------------------------------------
__global__ void fill_kernel(const int* __restrict__ ei) {
    int e = blockIdx.x * blockDim.x + threadIdx.x;
    if (e >= EP) return;
    int src = (e < EE) ? ei[e] : (e - EE);
    int dst = (e < EE) ? ei[EE + e] : (e - EE);
    int pos = g_offsets[dst] + atomicAdd(&g_cursor[dst], 1);
    g_csr_src[pos] = src;
}

// ---------------- segment softmax, 8 heads (writes exp val + inv) ------------------
__global__ void alpha8_kernel(const float* __restrict__ ssrc, const float* __restrict__ sdst,
                              float* __restrict__ val, float* __restrict__ inv) {
    int w = (blockIdx.x * blockDim.x + threadIdx.x) >> 5;
    int lane = threadIdx.x & 31;
    if (w >= NN) return;
    int beg = g_offsets[w], end = g_offsets[w + 1];
    float4 d0 = __ldg((const float4*)(sdst + w * 8));
    float4 d1 = __ldg((const float4*)(sdst + w * 8 + 4));
    float sdh[8] = {d0.x, d0.y, d0.z, d0.w, d1.x, d1.y, d1.z, d1.w};
    float m[8];
#pragma unroll
    for (int h = 0; h < 8; h++) m[h] = -1e30f;

    for (int p = beg + lane; p < end; p += 32) {
        int src = g_csr_src[p];
        float4 s0 = __ldg((const float4*)(ssrc + src * 8));
        float4 s1 = __ldg((const float4*)(ssrc + src * 8 + 4));
        float sv[8] = {s0.x, s0.y, s0.z, s0.w, s1.x, s1.y, s1.z, s1.w};
#pragma unroll
        for (int h = 0; h < 8; h++) {
            float v = sv[h] + sdh[h];
            v = v > 0.f ? v : LRELU * v;
            m[h] = fmaxf(m[h], v);
        }
    }
#pragma unroll
    for (int h = 0; h < 8; h++)
#pragma unroll
        for (int o = 16; o; o >>= 1) m[h] = fmaxf(m[h], __shfl_xor_sync(0xffffffffu, m[h], o));

    float s[8];
#pragma unroll
    for (int h = 0; h < 8; h++) s[h] = 0.f;
    for (int p = beg + lane; p < end; p += 32) {
        int src = g_csr_src[p];
        float4 s0 = __ldg((const float4*)(ssrc + src * 8));
        float4 s1 = __ldg((const float4*)(ssrc + src * 8 + 4));
        float sv[8] = {s0.x, s0.y, s0.z, s0.w, s1.x, s1.y, s1.z, s1.w};
#pragma unroll
        for (int h = 0; h < 8; h++) {
            float v = sv[h] + sdh[h];
            v = v > 0.f ? v : LRELU * v;
            float ex = __expf(v - m[h]);
            val[(size_t)h * EP + p] = ex;
            s[h] += ex;
        }
    }
#pragma unroll
    for (int h = 0; h < 8; h++)
#pragma unroll
        for (int o = 16; o; o >>= 1) s[h] += __shfl_xor_sync(0xffffffffu, s[h], o);
    if (lane == 0) {
#pragma unroll
        for (int h = 0; h < 8; h++) inv[w * 8 + h] = 1.0f / s[h];
    }
}

// ---------------- segment softmax, 1 head ------------------------------------------
__global__ void alpha1_kernel(const float* __restrict__ ssrc, const float* __restrict__ sdst,
                              float* __restrict__ val, float* __restrict__ inv) {
    int w = (blockIdx.x * blockDim.x + threadIdx.x) >> 5;
    int lane = threadIdx.x & 31;
    if (w >= NN) return;
    int beg = g_offsets[w], end = g_offsets[w + 1];
    float sdh = __ldg(sdst + w);
    float m = -1e30f;
    for (int p = beg + lane; p < end; p += 32) {
        float v = __ldg(ssrc + g_csr_src[p]) + sdh;
        v = v > 0.f ? v : LRELU * v;
        m = fmaxf(m, v);
    }
#pragma unroll
    for (int o = 16; o; o >>= 1) m = fmaxf(m, __shfl_xor_sync(0xffffffffu, m, o));
    float s = 0.f;
    for (int p = beg + lane; p < end; p += 32) {
        float v = __ldg(ssrc + g_csr_src[p]) + sdh;
        v = v > 0.f ? v : LRELU * v;
        float ex = __expf(v - m);
        val[p] = ex;
        s += ex;
    }
#pragma unroll
    for (int o = 16; o; o >>= 1) s += __shfl_xor_sync(0xffffffffu, s, o);
    if (lane == 0) inv[w] = 1.0f / s;
}

// ---------------- aggregation, Ftot=512, fp16 in/out (R13 style) -------------------
__global__ __launch_bounds__(128) void aggregate512_kernel(const __half* __restrict__ Wh16,
                                                           const float* __restrict__ val,
                                                           const float* __restrict__ inv,
                                                           __half* __restrict__ out16) {
    int d = blockIdx.x;
    int t = threadIdx.x;
    int h = t >> 4;
    int beg = g_offsets[d], end = g_offsets[d + 1];
    const uint2* W2 = (const uint2*)Wh16;
    const float* vh = val + (size_t)h * EP;
    float4 acc = make_float4(0.f, 0.f, 0.f, 0.f);
    int p = beg;
    for (; p + 1 < end; p += 2) {
        int s0 = g_csr_src[p], s1 = g_csr_src[p + 1];
        float e0 = __ldg(&vh[p]);
        float e1 = __ldg(&vh[p + 1]);
        uint2 u0 = __ldg(&W2[(size_t)s0 * 128 + t]);
        uint2 u1 = __ldg(&W2[(size_t)s1 * 128 + t]);
        float2 a0 = __half22float2(*(__half2*)&u0.x);
        float2 b0 = __half22float2(*(__half2*)&u0.y);
        float2 a1 = __half22float2(*(__half2*)&u1.x);
        float2 b1 = __half22float2(*(__half2*)&u1.y);
        acc.x += e0 * a0.x + e1 * a1.x;
        acc.y += e0 * a0.y + e1 * a1.y;
        acc.z += e0 * b0.x + e1 * b1.x;
        acc.w += e0 * b0.y + e1 * b1.y;
    }
    if (p < end) {
        int s0 = g_csr_src[p];
        float e0 = __ldg(&vh[p]);
        uint2 u0 = __ldg(&W2[(size_t)s0 * 128 + t]);
        float2 a0 = __half22float2(*(__half2*)&u0.x);
        float2 b0 = __half22float2(*(__half2*)&u0.y);
        acc.x += e0 * a0.x; acc.y += e0 * a0.y;
        acc.z += e0 * b0.x; acc.w += e0 * b0.y;
    }
    float iv = __ldg(&inv[d * 8 + h]);
    acc.x *= iv; acc.y *= iv; acc.z *= iv; acc.w *= iv;
    acc.x = acc.x > 0.f ? acc.x : expm1f(acc.x);
    acc.y = acc.y > 0.f ? acc.y : expm1f(acc.y);
    acc.z = acc.z > 0.f ? acc.z : expm1f(acc.z);
    acc.w = acc.w > 0.f ? acc.w : expm1f(acc.w);
    __half2 lo = __floats2half2_rn(acc.x, acc.y);
    __half2 hi = __floats2half2_rn(acc.z, acc.w);
    uint2 u;
    u.x = *(unsigned*)&lo; u.y = *(unsigned*)&hi;
    ((uint2*)out16)[(size_t)d * 128 + t] = u;
}

// ---------------- aggregation layer 2 + fused elu + log_softmax --------------------
__global__ __launch_bounds__(64) void aggregate_l2_final_kernel(const __half* __restrict__ WhO,
                                                                const float* __restrict__ val,
                                                                const float* __restrict__ inv,
                                                                float* __restrict__ out) {
    __shared__ float wred[2][2];
    int d = blockIdx.x;
    int f = threadIdx.x;
    int wp_ = f >> 5, lane = f & 31;
    int beg = g_offsets[d], end = g_offsets[d + 1];
    float acc = 0.f;
    for (int p = beg; p < end; p++) {
        int src = g_csr_src[p];
        float ex = __ldg(&val[p]);
        if (f < OUTF) acc += ex * __half2float(WhO[(size_t)src * 64 + f]);
    }
    float v = -1e30f;
    if (f < OUTF) {
        float o = acc * __ldg(&inv[d]);
        v = o > 0.f ? o : expm1f(o);
    }
    float m = v;
#pragma unroll
    for (int o = 16; o; o >>= 1) m = fmaxf(m, __shfl_xor_sync(0xffffffffu, m, o));
    if (lane == 0) wred[0][wp_] = m;
    __syncthreads();
    m = fmaxf(wred[0][0], wred[0][1]);
    float e = (f < OUTF) ? __expf(v - m) : 0.f;
    float s = e;
#pragma unroll
    for (int o = 16; o; o >>= 1) s += __shfl_xor_sync(0xffffffffu, s, o);
    if (lane == 0) wred[1][wp_] = s;
    __syncthreads();
    s = wred[1][0] + wred[1][1];
    float l = logf(s) + m;
    if (f < OUTF) out[(size_t)d * OUTF + f] = v - l;
}

// ---------------- host orchestration -----------------------------------------------
extern "C" void kernel_launch(void* const* d_in, const int* in_sizes, int n_in,
                              void* d_out, int out_size) {
    const float* x    = (const float*)d_in[0];
    const int*   ei   = (const int*)d_in[1];
    const float* W0   = (const float*)d_in[2];
    const float* a0   = (const float*)d_in[3];
    const float* W1   = (const float*)d_in[4];
    const float* a1   = (const float*)d_in[5];
    const float* Wout = (const float*)d_in[6];
    const float* aout = (const float*)d_in[7];
    float* out = (float*)d_out;

    __half *Wc0h, *Wc1h, *WcOh, *x16, *Wh16, *WhO16, *h1h, *h2h;
    float *aPad, *ssrc, *sdst, *val, *inv;
    cudaGetSymbolAddress((void**)&Wc0h, g_Wc0h);
    cudaGetSymbolAddress((void**)&Wc1h, g_Wc1h);
    cudaGetSymbolAddress((void**)&WcOh, g_WcOh);
    cudaGetSymbolAddress((void**)&aPad, g_aPad);
    cudaGetSymbolAddress((void**)&x16, g_x16);
    cudaGetSymbolAddress((void**)&Wh16, g_Wh16);
    cudaGetSymbolAddress((void**)&WhO16, g_WhO16);
    cudaGetSymbolAddress((void**)&h1h, g_h1h);
    cudaGetSymbolAddress((void**)&h2h, g_h2h);
    cudaGetSymbolAddress((void**)&ssrc, g_ssrc);
    cudaGetSymbolAddress((void**)&sdst, g_sdst);
    cudaGetSymbolAddress((void**)&val, g_val);
    cudaGetSymbolAddress((void**)&inv, g_inv);

    static int smem_set = 0;
    if (!smem_set) {
        cudaFuncSetAttribute(gemm_h_kernel,
                             cudaFuncAttributeMaxDynamicSharedMemorySize, GEMM_SMEM_BYTES);
        cudaFuncSetAttribute(hist_gemm_kernel,
                             cudaFuncAttributeMaxDynamicSharedMemorySize, GEMM_SMEM_BYTES);
        smem_set = 1;
    }

    const int TB = 256;
    dim3 gh_grid(4, (NN + 127) / 128);
    dim3 gh_grid_out(1, (NN + 127) / 128);

    // 1-3: prep
    prep_main_kernel<<<13209, TB>>>(W0, x, aout);
    packW1_kernel<<<1024, TB>>>(W1);
    packWout_kernel<<<128, TB>>>(Wout);
    // 4: hist || gemm0 (+scores l0)
    hist_gemm_kernel<<<HIST_BLKS + 1564, TB, GEMM_SMEM_BYTES>>>(ei, x16, Wc0h, Wh16, a0, ssrc, sdst);
    // 5-6: scan, fill
    scan_kernel<<<1, 1024>>>();
    fill_kernel<<<(EP + TB - 1) / TB, TB>>>(ei);
    // 7-8: layer-0 edge phase
    alpha8_kernel<<<(NN + 7) / 8, 256>>>(ssrc, sdst, val, inv);
    aggregate512_kernel<<<NN, 128>>>(Wh16, val, inv, h1h);

    // ---- layer 1 ----
    gemm_h_kernel<<<gh_grid, 256, GEMM_SMEM_BYTES>>>(h1h, Wc1h, Wh16, NN, 512, 512,
                                                     a1, ssrc, sdst, 1);
    alpha8_kernel<<<(NN + 7) / 8, 256>>>(ssrc, sdst, val, inv);
    aggregate512_kernel<<<NN, 128>>>(Wh16, val, inv, h2h);

    // ---- layer 2 (scores fused into GEMM epilogue, fp16 WhO) ----
    gemm_h_kernel<<<gh_grid_out, 256, GEMM_SMEM_BYTES>>>(h2h, WcOh, WhO16, NN, 64, 512,
                                                         aPad, ssrc, sdst, 2);
    alpha1_kernel<<<(NN + 7) / 8, 256>>>(ssrc, sdst, val, inv);
    aggregate_l2_final_kernel<<<NN, 64>>>(WhO16, val, inv, out);
}

// round 16
// speedup vs baseline: 1.0464x; 1.0192x over previous
#include <cuda_runtime.h>
#include <cuda_bf16.h>
#include <cuda_fp16.h>
#include <math.h>
#include <stdint.h>

#define NN 50000
#define EE 800000
#define EP (EE + NN)   // 850000 edges incl. self loops
#define HEADS 8
#define HID 64
#define INF_ 256
#define OUTF 40
#define LRELU 0.2f

// ---------------- scratch ------------------------------------------------------
__device__ __half g_Wc0h[512 * 256];          // [n][k] n-major
__device__ __half g_Wc1h[512 * 512];
__device__ __half g_WcOh[64 * 512];
__device__ float  g_aPad[128];
__device__ __half g_x16[(size_t)NN * INF_];
__device__ __half g_Wh16[(size_t)NN * 512];
__device__ __half g_WhO16[(size_t)NN * 64];
__device__ __half g_h1h[(size_t)NN * 512];
__device__ __half g_h2h[(size_t)NN * 512];
__device__ float  g_ssrc[NN * HEADS];
__device__ float  g_sdst[NN * HEADS];
__device__ float  g_val[(size_t)EP * HEADS];
__device__ float  g_inv[NN * HEADS];
__device__ int    g_counts[NN];
__device__ int    g_offsets[NN + 1];
__device__ int    g_cursor[NN];
__device__ int    g_csr_src[EP];

// ---------------- prep --------------------------------------------------------
__global__ void prep_main_kernel(const float* __restrict__ W0, const float* __restrict__ x,
                                 const float* __restrict__ aout) {
    int b = blockIdx.x, tid = threadIdx.x;
    if (b < 512) {
        int idx = b * 256 + tid;
        int n = idx >> 8, k = idx & 255;
        int h = n >> 6, j = n & 63;
        g_Wc0h[idx] = __float2half_rn(W0[(size_t)h * 256 * 64 + (size_t)k * 64 + j]);
    } else if (b < 13012) {
        int i = (b - 512) * 256 + tid;
        if (i < NN * INF_ / 4) {
            float4 v = __ldg((const float4*)x + i);
            __half2 lo = __floats2half2_rn(v.x, v.y);
            __half2 hi = __floats2half2_rn(v.z, v.w);
            uint2 u; u.x = *(unsigned*)&lo; u.y = *(unsigned*)&hi;
            ((uint2*)g_x16)[i] = u;
        }
    } else if (b < 13208) {
        int i = (b - 13012) * 256 + tid;
        if (i < NN) { g_counts[i] = 0; g_cursor[i] = 0; }
    } else {
        if (tid < 64)  g_aPad[tid] = (tid < OUTF) ? aout[tid] : 0.f;
        else if (tid < 128) {
            int j = tid - 64;
            g_aPad[64 + j] = (j < OUTF) ? aout[OUTF + j] : 0.f;
        }
    }
}

__global__ void packW1_kernel(const float* __restrict__ W1) {
    int idx = blockIdx.x * 256 + threadIdx.x;
    int n = idx >> 9, k = idx & 511;
    int h = n >> 6, j = n & 63;
    g_Wc1h[idx] = __float2half_rn(W1[(size_t)h * 512 * 64 + (size_t)k * 64 + j]);
}

__global__ void packWout_kernel(const float* __restrict__ Wout) {
    int idx = blockIdx.x * 256 + threadIdx.x;
    int n = idx >> 9, k = idx & 511;
    g_WcOh[idx] = (n < OUTF) ? __float2half_rn(Wout[k * OUTF + n]) : __float2half_rn(0.f);
}

// ---------------- cp.async helpers ---------------------------------------------
__device__ __forceinline__ void cp16(uint32_t dst, const void* src, bool pred) {
    int sz = pred ? 16 : 0;
    asm volatile("cp.async.ca.shared.global [%0], [%1], 16, %2;\n"
                 :: "r"(dst), "l"(src), "r"(sz));
}
#define CP_COMMIT() asm volatile("cp.async.commit_group;\n" ::: "memory")
#define CP_WAIT0()  asm volatile("cp.async.wait_group 0;\n" ::: "memory")
#define CP_WAIT1()  asm volatile("cp.async.wait_group 1;\n" ::: "memory")

#define LDMX4(R0, R1, R2, R3, ADDR) \
    asm volatile("ldmatrix.sync.aligned.m8n8.x4.shared.b16 {%0,%1,%2,%3}, [%4];" \
                 : "=r"(R0), "=r"(R1), "=r"(R2), "=r"(R3) : "r"(ADDR))

// ---------------- FP16 GEMM body: BM=128 BN=128 BK=32, 3-stage, ldmatrix --------
#define APH 40
#define A_BYTES (128 * APH * 2)
#define STAGE_BYTES (2 * A_BYTES)
#define GEMM_SMEM_BYTES (STAGE_BYTES * 3)

__device__ __forceinline__ void gemm_body_h(const __half* __restrict__ A,
                                            const __half* __restrict__ B,
                                            __half* __restrict__ C16,
                                            int M, int Nc, int K,
                                            int bxx, int byy, char* smc,
                                            const float* __restrict__ avec,
                                            float* __restrict__ ssrc,
                                            float* __restrict__ sdst,
                                            int score_mode) {
    int tid = threadIdx.x;
    int wid = tid >> 5, lane = tid & 31;
    int ly = lane >> 2, lx = lane & 3;
    int wm = wid >> 1, wn = wid & 1;
    int bm = byy * 128, bn = bxx * 128;

    uint32_t sbase = (uint32_t)__cvta_generic_to_shared(smc);

    float c[2][8][4];
#pragma unroll
    for (int i = 0; i < 2; i++)
#pragma unroll
        for (int j = 0; j < 8; j++)
#pragma unroll
            for (int q = 0; q < 4; q++) c[i][j][q] = 0.f;

    int r0 = tid >> 2, q0 = tid & 3;
    int r1 = (tid + 256) >> 2, q1 = (tid + 256) & 3;
    bool ap0 = (bm + r0) < M, ap1 = (bm + r1) < M;
    bool bpr0 = (bn + r0) < Nc, bpr1 = (bn + r1) < Nc;

    // ldmatrix per-thread element offsets (halves), add kk + stage base later.
    int lrow = lane & 7;               // row within 8x8 tile
    int lhi  = (lane >> 3) & 1;        // +8 rows for tiles 1,3
    int lkk  = (lane >> 4) * 8;        // +8 k for tiles 2,3
    uint32_t aoff[2], boff[4];
#pragma unroll
    for (int mt = 0; mt < 2; mt++)
        aoff[mt] = (uint32_t)(((wm * 32 + mt * 16 + lrow + lhi * 8) * APH + lkk) * 2);
#pragma unroll
    for (int g = 0; g < 4; g++)
        boff[g] = (uint32_t)(A_BYTES + ((wn * 64 + g * 16 + lrow + lhi * 8) * APH + lkk) * 2);

#define ISSUE(S, k0) do { \
        cp16(sbase + (S) * STAGE_BYTES + r0 * 80 + q0 * 16, \
             A + (size_t)(bm + r0) * K + (k0) + q0 * 8, ap0); \
        cp16(sbase + (S) * STAGE_BYTES + r1 * 80 + q1 * 16, \
             A + (size_t)(bm + r1) * K + (k0) + q1 * 8, ap1); \
        cp16(sbase + (S) * STAGE_BYTES + A_BYTES + r0 * 80 + q0 * 16, \
             B + (size_t)(bn + r0) * K + (k0) + q0 * 8, bpr0); \
        cp16(sbase + (S) * STAGE_BYTES + A_BYTES + r1 * 80 + q1 * 16, \
             B + (size_t)(bn + r1) * K + (k0) + q1 * 8, bpr1); \
        CP_COMMIT(); \
    } while (0)

#define BODY(S, t) do { \
        if ((t) + 2 < ntiles) { CP_WAIT1(); } else { CP_WAIT0(); } \
        __syncthreads(); \
        if ((t) + 2 < ntiles) ISSUE(((S) + 2) % 3, ((t) + 2) * 32); \
        uint32_t stg = sbase + (S) * STAGE_BYTES; \
        _Pragma("unroll") \
        for (int kk = 0; kk < 32; kk += 16) { \
            unsigned af[2][4]; \
            LDMX4(af[0][0], af[0][1], af[0][2], af[0][3], stg + aoff[0] + kk * 2); \
            LDMX4(af[1][0], af[1][1], af[1][2], af[1][3], stg + aoff[1] + kk * 2); \
            unsigned bf[8][2]; \
            _Pragma("unroll") \
            for (int g = 0; g < 4; g++) { \
                unsigned t0, t1, t2, t3; \
                LDMX4(t0, t1, t2, t3, stg + boff[g] + kk * 2); \
                bf[2 * g][0] = t0; bf[2 * g + 1][0] = t1; \
                bf[2 * g][1] = t2; bf[2 * g + 1][1] = t3; \
            } \
            _Pragma("unroll") \
            for (int mt = 0; mt < 2; mt++) \
                _Pragma("unroll") \
                for (int nt = 0; nt < 8; nt++) { \
                    asm volatile( \
                        "mma.sync.aligned.m16n8k16.row.col.f32.f16.f16.f32 " \
                        "{%0,%1,%2,%3}, {%4,%5,%6,%7}, {%8,%9}, {%0,%1,%2,%3};\n" \
                        : "+f"(c[mt][nt][0]), "+f"(c[mt][nt][1]), \
                          "+f"(c[mt][nt][2]), "+f"(c[mt][nt][3]) \
                        : "r"(af[mt][0]), "r"(af[mt][1]), "r"(af[mt][2]), "r"(af[mt][3]), \
                          "r"(bf[nt][0]), "r"(bf[nt][1])); \
                } \
        } \
    } while (0)

    int ntiles = K / 32;
    ISSUE(0, 0);
    ISSUE(1, 32);

    int nfull = ntiles - (ntiles % 3);
    for (int t = 0; t < nfull; t += 3) {
        BODY(0, t);
        BODY(1, t + 1);
        BODY(2, t + 2);
    }
    if (ntiles % 3 >= 1) BODY(0, nfull);
    if (ntiles % 3 == 2) BODY(1, nfull + 1);
#undef BODY
#undef ISSUE

    __syncthreads();
    if (C16) {
#pragma unroll
        for (int mt = 0; mt < 2; mt++)
#pragma unroll
            for (int nt = 0; nt < 8; nt++) {
                int rr0 = bm + wm * 32 + mt * 16 + ly;
                int col = bn + wn * 64 + nt * 8 + 2 * lx;
                if (col < Nc) {
                    if (rr0 < M)
                        *(__half2*)(C16 + (size_t)rr0 * Nc + col) =
                            __floats2half2_rn(c[mt][nt][0], c[mt][nt][1]);
                    int rr1 = rr0 + 8;
                    if (rr1 < M)
                        *(__half2*)(C16 + (size_t)rr1 * Nc + col) =
                            __floats2half2_rn(c[mt][nt][2], c[mt][nt][3]);
                }
            }
    }

    // ---- fused attention-score epilogues ----
    if (score_mode == 1 || (score_mode == 2 && wn == 0)) {
        const float* aH = (score_mode == 1) ? (avec + (2 * bxx + wn) * 128) : avec;
        float accs[2][2], accd[2][2];
#pragma unroll
        for (int mt = 0; mt < 2; mt++) { accs[mt][0] = accs[mt][1] = accd[mt][0] = accd[mt][1] = 0.f; }
#pragma unroll
        for (int nt = 0; nt < 8; nt++) {
            int jc = nt * 8 + 2 * lx;
            float a0s = __ldg(aH + jc), a1s = __ldg(aH + jc + 1);
            float a0d = __ldg(aH + 64 + jc), a1d = __ldg(aH + 64 + jc + 1);
#pragma unroll
            for (int mt = 0; mt < 2; mt++) {
                accs[mt][0] += c[mt][nt][0] * a0s + c[mt][nt][1] * a1s;
                accd[mt][0] += c[mt][nt][0] * a0d + c[mt][nt][1] * a1d;
                accs[mt][1] += c[mt][nt][2] * a0s + c[mt][nt][3] * a1s;
                accd[mt][1] += c[mt][nt][2] * a0d + c[mt][nt][3] * a1d;
            }
        }
#pragma unroll
        for (int mt = 0; mt < 2; mt++)
#pragma unroll
            for (int hf = 0; hf < 2; hf++) {
                accs[mt][hf] += __shfl_xor_sync(0xffffffffu, accs[mt][hf], 1);
                accs[mt][hf] += __shfl_xor_sync(0xffffffffu, accs[mt][hf], 2);
                accd[mt][hf] += __shfl_xor_sync(0xffffffffu, accd[mt][hf], 1);
                accd[mt][hf] += __shfl_xor_sync(0xffffffffu, accd[mt][hf], 2);
            }
        if (lx == 0) {
#pragma unroll
            for (int mt = 0; mt < 2; mt++)
#pragma unroll
                for (int hf = 0; hf < 2; hf++) {
                    int row = bm + wm * 32 + mt * 16 + ly + hf * 8;
                    if (row < M) {
                        if (score_mode == 1) {
                            int head = 2 * bxx + wn;
                            ssrc[row * 8 + head] = accs[mt][hf];
                            sdst[row * 8 + head] = accd[mt][hf];
                        } else {
                            ssrc[row] = accs[mt][hf];
                            sdst[row] = accd[mt][hf];
                        }
                    }
                }
        }
    }
}

// ---------------- standalone GEMM ------------------------------------------------
__global__ __launch_bounds__(256) void gemm_h_kernel(const __half* __restrict__ A,
                                                     const __half* __restrict__ B,
                                                     __half* __restrict__ C16,
                                                     int M, int Nc, int K,
                                                     const float* __restrict__ avec,
                                                     float* __restrict__ ssrc,
                                                     float* __restrict__ sdst,
                                                     int score_mode) {
    extern __shared__ char smc[];
    gemm_body_h(A, B, C16, M, Nc, K, blockIdx.x, blockIdx.y, smc, avec, ssrc, sdst, score_mode);
}

// ---------------- fused hist + gemm0 ---------------------------------------------
#define HIST_BLKS 3321
__global__ __launch_bounds__(256) void hist_gemm_kernel(const int* __restrict__ ei,
                                                        const __half* __restrict__ A,
                                                        const __half* __restrict__ B,
                                                        __half* __restrict__ C16,
                                                        const float* __restrict__ avec,
                                                        float* __restrict__ ssrc,
                                                        float* __restrict__ sdst) {
    extern __shared__ char smc[];
    int b = blockIdx.x;
    if (b < HIST_BLKS) {
        int e = b * 256 + threadIdx.x;
        if (e < EP) {
            int dst = (e < EE) ? ei[EE + e] : (e - EE);
            atomicAdd(&g_counts[dst], 1);
        }
        return;
    }
    int g = b - HIST_BLKS;
    gemm_body_h(A, B, C16, NN, 512, INF_, g & 3, g >> 2, smc, avec, ssrc, sdst, 1);
}

// ---------------- fast single-block scan ------------------------------------------
__global__ void scan_kernel() {
    __shared__ int ws[33];
    int tid = threadIdx.x;
    int w = tid >> 5, lane = tid & 31;
    int carry = 0;
    for (int base = 0; base < NN; base += 1024) {
        int i = base + tid;
        int x = (i < NN) ? g_counts[i] : 0;
        int inc = x;
#pragma unroll
        for (int o = 1; o < 32; o <<= 1) {
            int t = __shfl_up_sync(0xffffffffu, inc, o);
            if (lane >= o) inc += t;
        }
        if (lane == 31) ws[w] = inc;
        __syncthreads();
        if (w == 0) {
            int t = (lane < 32) ? ws[lane] : 0;
            int ti = t;
#pragma unroll
            for (int o = 1; o < 32; o <<= 1) {
                int u = __shfl_up_sync(0xffffffffu, ti, o);
                if (lane >= o) ti += u;
            }
            ws[lane] = ti - t;
            if (lane == 31) ws[32] = ti;
        }
        __syncthreads();
        int excl = inc - x + ws[w] + carry;
        if (i < NN) g_offsets[i] = excl;
        carry += ws[32];
        __syncthreads();
    }
    if (tid == 0) g_offsets[NN] = carry;
}

// ---------------- fill -------------------------------------------------------------
__global__ void fill_kernel(const int* __restrict__ ei) {
    int e = blockIdx.x * blockDim.x + threadIdx.x;
    if (e >= EP) return;
    int src = (e < EE) ? ei[e] : (e - EE);
    int dst = (e < EE) ? ei[EE + e] : (e - EE);
    int pos = g_offsets[dst] + atomicAdd(&g_cursor[dst], 1);
    g_csr_src[pos] = src;
}

// ---------------- segment softmax, 8 heads -----------------------------------------
__global__ void alpha8_kernel(const float* __restrict__ ssrc, const float* __restrict__ sdst,
                              float* __restrict__ val, float* __restrict__ inv) {
    int w = (blockIdx.x * blockDim.x + threadIdx.x) >> 5;
    int lane = threadIdx.x & 31;
    if (w >= NN) return;
    int beg = g_offsets[w], end = g_offsets[w + 1];
    float4 d0 = __ldg((const float4*)(sdst + w * 8));
    float4 d1 = __ldg((const float4*)(sdst + w * 8 + 4));
    float sdh[8] = {d0.x, d0.y, d0.z, d0.w, d1.x, d1.y, d1.z, d1.w};
    float m[8];
#pragma unroll
    for (int h = 0; h < 8; h++) m[h] = -1e30f;

    for (int p = beg + lane; p < end; p += 32) {
        int src = g_csr_src[p];
        float4 s0 = __ldg((const float4*)(ssrc + src * 8));
        float4 s1 = __ldg((const float4*)(ssrc + src * 8 + 4));
        float sv[8] = {s0.x, s0.y, s0.z, s0.w, s1.x, s1.y, s1.z, s1.w};
#pragma unroll
        for (int h = 0; h < 8; h++) {
            float v = sv[h] + sdh[h];
            v = v > 0.f ? v : LRELU * v;
            m[h] = fmaxf(m[h], v);
        }
    }
#pragma unroll
    for (int h = 0; h < 8; h++)
#pragma unroll
        for (int o = 16; o; o >>= 1) m[h] = fmaxf(m[h], __shfl_xor_sync(0xffffffffu, m[h], o));

    float s[8];
#pragma unroll
    for (int h = 0; h < 8; h++) s[h] = 0.f;
    for (int p = beg + lane; p < end; p += 32) {
        int src = g_csr_src[p];
        float4 s0 = __ldg((const float4*)(ssrc + src * 8));
        float4 s1 = __ldg((const float4*)(ssrc + src * 8 + 4));
        float sv[8] = {s0.x, s0.y, s0.z, s0.w, s1.x, s1.y, s1.z, s1.w};
#pragma unroll
        for (int h = 0; h < 8; h++) {
            float v = sv[h] + sdh[h];
            v = v > 0.f ? v : LRELU * v;
            float ex = __expf(v - m[h]);
            val[(size_t)h * EP + p] = ex;
            s[h] += ex;
        }
    }
#pragma unroll
    for (int h = 0; h < 8; h++)
#pragma unroll
        for (int o = 16; o; o >>= 1) s[h] += __shfl_xor_sync(0xffffffffu, s[h], o);
    if (lane == 0) {
#pragma unroll
        for (int h = 0; h < 8; h++) inv[w * 8 + h] = 1.0f / s[h];
    }
}

// ---------------- segment softmax, 1 head ------------------------------------------
__global__ void alpha1_kernel(const float* __restrict__ ssrc, const float* __restrict__ sdst,
                              float* __restrict__ val, float* __restrict__ inv) {
    int w = (blockIdx.x * blockDim.x + threadIdx.x) >> 5;
    int lane = threadIdx.x & 31;
    if (w >= NN) return;
    int beg = g_offsets[w], end = g_offsets[w + 1];
    float sdh = __ldg(sdst + w);
    float m = -1e30f;
    for (int p = beg + lane; p < end; p += 32) {
        float v = __ldg(ssrc + g_csr_src[p]) + sdh;
        v = v > 0.f ? v : LRELU * v;
        m = fmaxf(m, v);
    }
#pragma unroll
    for (int o = 16; o; o >>= 1) m = fmaxf(m, __shfl_xor_sync(0xffffffffu, m, o));
    float s = 0.f;
    for (int p = beg + lane; p < end; p += 32) {
        float v = __ldg(ssrc + g_csr_src[p]) + sdh;
        v = v > 0.f ? v : LRELU * v;
        float ex = __expf(v - m);
        val[p] = ex;
        s += ex;
    }
#pragma unroll
    for (int o = 16; o; o >>= 1) s += __shfl_xor_sync(0xffffffffu, s, o);
    if (lane == 0) inv[w] = 1.0f / s;
}

// ---------------- aggregation, Ftot=512, fp16 in/out -------------------------------
__global__ __launch_bounds__(128) void aggregate512_kernel(const __half* __restrict__ Wh16,
                                                           const float* __restrict__ val,
                                                           const float* __restrict__ inv,
                                                           __half* __restrict__ out16) {
    int d = blockIdx.x;
    int t = threadIdx.x;
    int h = t >> 4;
    int beg = g_offsets[d], end = g_offsets[d + 1];
    const uint2* W2 = (const uint2*)Wh16;
    const float* vh = val + (size_t)h * EP;
    float4 acc = make_float4(0.f, 0.f, 0.f, 0.f);
    int p = beg;
    for (; p + 1 < end; p += 2) {
        int s0 = g_csr_src[p], s1 = g_csr_src[p + 1];
        float e0 = __ldg(&vh[p]);
        float e1 = __ldg(&vh[p + 1]);
        uint2 u0 = __ldg(&W2[(size_t)s0 * 128 + t]);
        uint2 u1 = __ldg(&W2[(size_t)s1 * 128 + t]);
        float2 a0 = __half22float2(*(__half2*)&u0.x);
        float2 b0 = __half22float2(*(__half2*)&u0.y);
        float2 a1 = __half22float2(*(__half2*)&u1.x);
        float2 b1 = __half22float2(*(__half2*)&u1.y);
        acc.x += e0 * a0.x + e1 * a1.x;
        acc.y += e0 * a0.y + e1 * a1.y;
        acc.z += e0 * b0.x + e1 * b1.x;
        acc.w += e0 * b0.y + e1 * b1.y;
    }
    if (p < end) {
        int s0 = g_csr_src[p];
        float e0 = __ldg(&vh[p]);
        uint2 u0 = __ldg(&W2[(size_t)s0 * 128 + t]);
        float2 a0 = __half22float2(*(__half2*)&u0.x);
        float2 b0 = __half22float2(*(__half2*)&u0.y);
        acc.x += e0 * a0.x; acc.y += e0 * a0.y;
        acc.z += e0 * b0.x; acc.w += e0 * b0.y;
    }
    float iv = __ldg(&inv[d * 8 + h]);
    acc.x *= iv; acc.y *= iv; acc.z *= iv; acc.w *= iv;
    acc.x = acc.x > 0.f ? acc.x : expm1f(acc.x);
    acc.y = acc.y > 0.f ? acc.y : expm1f(acc.y);
    acc.z = acc.z > 0.f ? acc.z : expm1f(acc.z);
    acc.w = acc.w > 0.f ? acc.w : expm1f(acc.w);
    __half2 lo = __floats2half2_rn(acc.x, acc.y);
    __half2 hi = __floats2half2_rn(acc.z, acc.w);
    uint2 u;
    u.x = *(unsigned*)&lo; u.y = *(unsigned*)&hi;
    ((uint2*)out16)[(size_t)d * 128 + t] = u;
}

// ---------------- aggregation layer 2 + fused elu + log_softmax --------------------
__global__ __launch_bounds__(64) void aggregate_l2_final_kernel(const __half* __restrict__ WhO,
                                                                const float* __restrict__ val,
                                                                const float* __restrict__ inv,
                                                                float* __restrict__ out) {
    __shared__ float wred[2][2];
    int d = blockIdx.x;
    int f = threadIdx.x;
    int wp_ = f >> 5, lane = f & 31;
    int beg = g_offsets[d], end = g_offsets[d + 1];
    float acc = 0.f;
    for (int p = beg; p < end; p++) {
        int src = g_csr_src[p];
        float ex = __ldg(&val[p]);
        if (f < OUTF) acc += ex * __half2float(WhO[(size_t)src * 64 + f]);
    }
    float v = -1e30f;
    if (f < OUTF) {
        float o = acc * __ldg(&inv[d]);
        v = o > 0.f ? o : expm1f(o);
    }
    float m = v;
#pragma unroll
    for (int o = 16; o; o >>= 1) m = fmaxf(m, __shfl_xor_sync(0xffffffffu, m, o));
    if (lane == 0) wred[0][wp_] = m;
    __syncthreads();
    m = fmaxf(wred[0][0], wred[0][1]);
    float e = (f < OUTF) ? __expf(v - m) : 0.f;
    float s = e;
#pragma unroll
    for (int o = 16; o; o >>= 1) s += __shfl_xor_sync(0xffffffffu, s, o);
    if (lane == 0) wred[1][wp_] = s;
    __syncthreads();
    s = wred[1][0] + wred[1][1];
    float l = logf(s) + m;
    if (f < OUTF) out[(size_t)d * OUTF + f] = v - l;
}

// ---------------- host orchestration -----------------------------------------------
extern "C" void kernel_launch(void* const* d_in, const int* in_sizes, int n_in,
                              void* d_out, int out_size) {
    const float* x    = (const float*)d_in[0];
    const int*   ei   = (const int*)d_in[1];
    const float* W0   = (const float*)d_in[2];
    const float* a0   = (const float*)d_in[3];
    const float* W1   = (const float*)d_in[4];
    const float* a1   = (const float*)d_in[5];
    const float* Wout = (const float*)d_in[6];
    const float* aout = (const float*)d_in[7];
    float* out = (float*)d_out;

    __half *Wc0h, *Wc1h, *WcOh, *x16, *Wh16, *WhO16, *h1h, *h2h;
    float *aPad, *ssrc, *sdst, *val, *inv;
    cudaGetSymbolAddress((void**)&Wc0h, g_Wc0h);
    cudaGetSymbolAddress((void**)&Wc1h, g_Wc1h);
    cudaGetSymbolAddress((void**)&WcOh, g_WcOh);
    cudaGetSymbolAddress((void**)&aPad, g_aPad);
    cudaGetSymbolAddress((void**)&x16, g_x16);
    cudaGetSymbolAddress((void**)&Wh16, g_Wh16);
    cudaGetSymbolAddress((void**)&WhO16, g_WhO16);
    cudaGetSymbolAddress((void**)&h1h, g_h1h);
    cudaGetSymbolAddress((void**)&h2h, g_h2h);
    cudaGetSymbolAddress((void**)&ssrc, g_ssrc);
    cudaGetSymbolAddress((void**)&sdst, g_sdst);
    cudaGetSymbolAddress((void**)&val, g_val);
    cudaGetSymbolAddress((void**)&inv, g_inv);

    static int smem_set = 0;
    if (!smem_set) {
        cudaFuncSetAttribute(gemm_h_kernel,
                             cudaFuncAttributeMaxDynamicSharedMemorySize, GEMM_SMEM_BYTES);
        cudaFuncSetAttribute(hist_gemm_kernel,
                             cudaFuncAttributeMaxDynamicSharedMemorySize, GEMM_SMEM_BYTES);
        smem_set = 1;
    }

    const int TB = 256;
    dim3 gh_grid(4, (NN + 127) / 128);
    dim3 gh_grid_out(1, (NN + 127) / 128);

    // 1-3: prep
    prep_main_kernel<<<13209, TB>>>(W0, x, aout);
    packW1_kernel<<<1024, TB>>>(W1);
    packWout_kernel<<<128, TB>>>(Wout);
    // 4: hist || gemm0 (+scores l0)
    hist_gemm_kernel<<<HIST_BLKS + 1564, TB, GEMM_SMEM_BYTES>>>(ei, x16, Wc0h, Wh16, a0, ssrc, sdst);
    // 5-6: scan, fill
    scan_kernel<<<1, 1024>>>();
    fill_kernel<<<(EP + TB - 1) / TB, TB>>>(ei);
    // 7-8: layer-0 edge phase
    alpha8_kernel<<<(NN + 7) / 8, 256>>>(ssrc, sdst, val, inv);
    aggregate512_kernel<<<NN, 128>>>(Wh16, val, inv, h1h);

    // ---- layer 1 ----
    gemm_h_kernel<<<gh_grid, 256, GEMM_SMEM_BYTES>>>(h1h, Wc1h, Wh16, NN, 512, 512,
                                                     a1, ssrc, sdst, 1);
    alpha8_kernel<<<(NN + 7) / 8, 256>>>(ssrc, sdst, val, inv);
    aggregate512_kernel<<<NN, 128>>>(Wh16, val, inv, h2h);

    // ---- layer 2 ----
    gemm_h_kernel<<<gh_grid_out, 256, GEMM_SMEM_BYTES>>>(h2h, WcOh, WhO16, NN, 64, 512,
                                                         aPad, ssrc, sdst, 2);
    alpha1_kernel<<<(NN + 7) / 8, 256>>>(ssrc, sdst, val, inv);
    aggregate_l2_final_kernel<<<NN, 64>>>(WhO16, val, inv, out);
}